// round 5
// baseline (speedup 1.0000x reference)
#include <cuda_runtime.h>
#include <cuda_bf16.h>
#include <cstdint>

// ---------------- problem constants ----------------
#define R_TOTAL 16384   // B*L
#define KDIM    1024    // D
#define NDEP    500     // MLP_DIM
#define NTOT    1000
#define NPAD    1024    // padded N
#define KSTACK  3072    // [A_hi*W_hi | A_hi*W_lo | A_lo*W_hi]
#define KA      2048    // A storage: [hi | lo]
#define NEG_SLOPE 0.01f

#define BK      64      // k per stage (128 bytes bf16)
#define KITERS  (KSTACK / BK)   // 48
#define PIPE    4

// ---------------- device scratch ----------------
__device__ __nv_bfloat16 gA[(size_t)R_TOTAL * KA];   // 64 MB
__device__ __nv_bfloat16 gW[(size_t)NPAD * KSTACK];  // 6 MB (row n, K-major, zero-padded)
__device__ float g_scores[R_TOTAL * 4];              // {dep0,dep1,head0,head1}

// ---------------- PTX helpers ----------------
__device__ __forceinline__ uint32_t smem_u32(const void* p) {
    uint32_t a;
    asm("{ .reg .u64 t; cvta.to.shared.u64 t, %1; cvt.u32.u64 %0, t; }" : "=r"(a) : "l"(p));
    return a;
}
__device__ __forceinline__ void cp_async16(uint32_t saddr, const void* gptr) {
    asm volatile("cp.async.cg.shared.global [%0], [%1], 16;" :: "r"(saddr), "l"(gptr) : "memory");
}
#define CP_COMMIT() asm volatile("cp.async.commit_group;" ::: "memory")
#define CP_WAIT2()  asm volatile("cp.async.wait_group 2;" ::: "memory")

__device__ __forceinline__ void ldsm_x4(uint32_t* r, uint32_t addr) {
    asm volatile("ldmatrix.sync.aligned.m8n8.x4.shared.b16 {%0,%1,%2,%3}, [%4];"
        : "=r"(r[0]), "=r"(r[1]), "=r"(r[2]), "=r"(r[3]) : "r"(addr));
}
__device__ __forceinline__ void mma_bf16(float* d, const uint32_t* a, uint32_t b0, uint32_t b1) {
    asm volatile("mma.sync.aligned.m16n8k16.row.col.f32.bf16.bf16.f32 "
        "{%0,%1,%2,%3}, {%4,%5,%6,%7}, {%8,%9}, {%0,%1,%2,%3};"
        : "+f"(d[0]), "+f"(d[1]), "+f"(d[2]), "+f"(d[3])
        : "r"(a[0]), "r"(a[1]), "r"(a[2]), "r"(a[3]), "r"(b0), "r"(b1));
}

// ---------------- conversion kernels ----------------
__global__ __launch_bounds__(256) void convert_A(const float* __restrict__ A) {
    size_t idx = ((size_t)blockIdx.x * 256 + threadIdx.x) * 4;
    const float4 v = *reinterpret_cast<const float4*>(A + idx);
    const size_t m = idx >> 10, k = idx & 1023;
    float f[4] = {v.x, v.y, v.z, v.w};
    union { __nv_bfloat16 b[4]; unsigned long long u; } ph, pl;
    #pragma unroll
    for (int i = 0; i < 4; i++) {
        ph.b[i] = __float2bfloat16_rn(f[i]);
        pl.b[i] = __float2bfloat16_rn(f[i] - __bfloat162float(ph.b[i]));
    }
    *reinterpret_cast<unsigned long long*>(&gA[m * KA + k])        = ph.u;
    *reinterpret_cast<unsigned long long*>(&gA[m * KA + 1024 + k]) = pl.u;
}

__global__ __launch_bounds__(256) void convert_W(const float* __restrict__ Wd,
                                                 const float* __restrict__ Wh) {
    const int n = blockIdx.x;  // 0..1023
    for (int k = threadIdx.x; k < KDIM; k += 256) {
        float v = 0.f;
        if (n < NDEP)      v = Wd[(size_t)k * NDEP + n];
        else if (n < NTOT) v = Wh[(size_t)k * NDEP + (n - NDEP)];
        __nv_bfloat16 h = __float2bfloat16_rn(v);
        __nv_bfloat16 l = __float2bfloat16_rn(v - __bfloat162float(h));
        const size_t base = (size_t)n * KSTACK;
        gW[base + k] = h;
        gW[base + 1024 + k] = l;
        gW[base + 2048 + k] = h;
    }
}

__global__ __launch_bounds__(256) void zero_scores() {
    const int i = (blockIdx.x * 256 + threadIdx.x) * 4;
    *reinterpret_cast<float4*>(&g_scores[i]) = make_float4(0.f, 0.f, 0.f, 0.f);
}

// ---------------- mma.sync GEMM + fused scores ----------------
// grid (8 n-blocks, 128 m-blocks), 512 threads, 1 CTA/SM.
// CTA tile 128x128, warp grid 4x4 (warp tile 32x32), 4-stage cp.async,
// register double-buffered ldmatrix fragments.
#define S_STAGE   32768                     // A 16K + B 16K per stage
#define S_BOFF    16384
#define S_BIAS    (PIPE * S_STAGE)          // 131072
#define S_WC0     (S_BIAS + 512)
#define S_WC1     (S_WC0 + 512)
#define SMEM_TOTAL (S_WC1 + 512)            // 132608

__global__ __launch_bounds__(512, 1) void gemm_mma(const float* __restrict__ bd,
                                                   const float* __restrict__ bh,
                                                   const float* __restrict__ Wc) {
    extern __shared__ char smem[];
    const uint32_t sbase = smem_u32(smem);
    const int tid  = threadIdx.x;
    const int wid  = tid >> 5, lane = tid & 31;
    const int wm   = wid & 3,  wn   = wid >> 2;     // 4 x 4 warp grid
    const int n0g  = blockIdx.x * 128;
    const int row0 = blockIdx.y * 128;

    float* s_bias = (float*)(smem + S_BIAS);
    float* s_wc0  = (float*)(smem + S_WC0);
    float* s_wc1  = (float*)(smem + S_WC1);
    if (tid < 128) {
        const int n = n0g + tid;
        float b = 0.f, w0 = 0.f, w1 = 0.f;
        if (n < NDEP)      b = bd[n];
        else if (n < NTOT) b = bh[n - NDEP];
        if (n < NTOT) { w0 = Wc[n * 2]; w1 = Wc[n * 2 + 1]; }
        s_bias[tid] = b; s_wc0[tid] = w0; s_wc1[tid] = w1;
    }

    const char* Abase = (const char*)gA + (size_t)row0 * (KA * 2);
    const char* Bbase = (const char*)gW + (size_t)n0g * (KSTACK * 2);

    auto issue_stage = [&](int kit) {
        const int kg = kit * BK;
        const int ka = (kg < 1024) ? kg : kg - 1024;   // A plane remap (hi reused)
        const uint32_t sa = sbase + (kit % PIPE) * S_STAGE;
        const uint32_t sb = sa + S_BOFF;
        const char* ag = Abase + (size_t)ka * 2;
        const char* bg = Bbase + (size_t)kg * 2;
        #pragma unroll
        for (int i = 0; i < 2; i++) {
            const int seg = tid + i * 512;             // 0..1023
            const int r = seg >> 3, s = seg & 7;
            const uint32_t off = (uint32_t)r * 128u + ((uint32_t)(s * 16) ^ (((uint32_t)r & 7u) << 4));
            cp_async16(sa + off, ag + (size_t)r * (KA * 2) + s * 16);
            cp_async16(sb + off, bg + (size_t)r * (KSTACK * 2) + s * 16);
        }
    };

    // prologue: 3 stages in flight
    issue_stage(0); CP_COMMIT();
    issue_stage(1); CP_COMMIT();
    issue_stage(2); CP_COMMIT();

    float acc[2][4][4];
    #pragma unroll
    for (int mi = 0; mi < 2; mi++)
        #pragma unroll
        for (int nj = 0; nj < 4; nj++)
            #pragma unroll
            for (int c = 0; c < 4; c++) acc[mi][nj][c] = 0.f;

    const int lane15 = lane & 15;
    const int laneh  = lane >> 4;
    const uint32_t xm = ((uint32_t)lane & 7u) << 4;
    const uint32_t a_row0 = (uint32_t)(wm * 32 + lane15) * 128u;
    const uint32_t a_row1 = a_row0 + 16u * 128u;
    const uint32_t b_row0 = (uint32_t)(wn * 32 + lane15) * 128u;
    const uint32_t b_row1 = b_row0 + 16u * 128u;

    uint32_t af[2][2][4], bf[2][2][4];   // [buf][group][4]

    #pragma unroll 1
    for (int kit = 0; kit < KITERS; kit++) {
        CP_WAIT2();
        __syncthreads();
        if (kit + 3 < KITERS) issue_stage(kit + 3);
        CP_COMMIT();   // empty commits at tail keep wait_group accounting valid

        const uint32_t sa = sbase + (kit % PIPE) * S_STAGE;
        const uint32_t sb = sa + S_BOFF;

        // preload kk=0 fragments
        {
            const uint32_t cc = ((uint32_t)(laneh * 16)) ^ xm;
            ldsm_x4(af[0][0], sa + a_row0 + cc);
            ldsm_x4(af[0][1], sa + a_row1 + cc);
            ldsm_x4(bf[0][0], sb + b_row0 + cc);
            ldsm_x4(bf[0][1], sb + b_row1 + cc);
        }
        #pragma unroll
        for (int kk = 0; kk < 4; kk++) {
            const int cur = kk & 1, nxt = cur ^ 1;
            if (kk < 3) {
                const uint32_t cc = ((uint32_t)((kk + 1) * 32 + laneh * 16)) ^ xm;
                ldsm_x4(af[nxt][0], sa + a_row0 + cc);
                ldsm_x4(af[nxt][1], sa + a_row1 + cc);
                ldsm_x4(bf[nxt][0], sb + b_row0 + cc);
                ldsm_x4(bf[nxt][1], sb + b_row1 + cc);
            }
            #pragma unroll
            for (int mi = 0; mi < 2; mi++) {
                #pragma unroll
                for (int nj = 0; nj < 4; nj++) {
                    const int ni2 = nj >> 1, w = nj & 1;
                    mma_bf16(acc[mi][nj], af[cur][mi], bf[cur][ni2][w], bf[cur][ni2][w + 2]);
                }
            }
        }
    }

    // ---- epilogue: bias + leaky + Wc collapse, lane reduce, atomic scores ----
    float p[2][2][4];
    #pragma unroll
    for (int mi = 0; mi < 2; mi++)
        #pragma unroll
        for (int h = 0; h < 2; h++)
            #pragma unroll
            for (int j = 0; j < 4; j++) p[mi][h][j] = 0.f;

    #pragma unroll
    for (int mi = 0; mi < 2; mi++) {
        #pragma unroll
        for (int nj = 0; nj < 4; nj++) {
            #pragma unroll
            for (int c = 0; c < 4; c++) {
                const int h = c >> 1, e = c & 1;
                const int nloc = wn * 32 + nj * 8 + (lane & 3) * 2 + e;
                const int n = n0g + nloc;
                const float v  = acc[mi][nj][c] + s_bias[nloc];
                const float lv = (v > 0.f) ? v : NEG_SLOPE * v;
                const int idx = (n < NDEP) ? 0 : 2;
                p[mi][h][idx]     += lv * s_wc0[nloc];
                p[mi][h][idx + 1] += lv * s_wc1[nloc];
            }
        }
    }

    #pragma unroll
    for (int mi = 0; mi < 2; mi++) {
        #pragma unroll
        for (int h = 0; h < 2; h++) {
            const int row = row0 + wm * 32 + mi * 16 + (lane >> 2) + 8 * h;
            #pragma unroll
            for (int j = 0; j < 4; j++) {
                float v = p[mi][h][j];
                v += __shfl_xor_sync(0xffffffffu, v, 1);
                v += __shfl_xor_sync(0xffffffffu, v, 2);
                if ((lane & 3) == 0) atomicAdd(&g_scores[(size_t)row * 4 + j], v);
            }
        }
    }
}

// ---------------- broadcast: 8 output rows per CTA ----------------
__global__ __launch_bounds__(256) void broadcast_kernel(const float* __restrict__ bc,
                                                        float* __restrict__ out) {
    const int r0    = blockIdx.x * 8;
    const int bbase = r0 & ~1023;
    const int j0    = threadIdx.x * 4;
    const float bc0 = bc[0], bc1 = bc[1];

    const float4 h0 = *reinterpret_cast<const float4*>(&g_scores[(size_t)(bbase + j0 + 0) * 4]);
    const float4 h1 = *reinterpret_cast<const float4*>(&g_scores[(size_t)(bbase + j0 + 1) * 4]);
    const float4 h2 = *reinterpret_cast<const float4*>(&g_scores[(size_t)(bbase + j0 + 2) * 4]);
    const float4 h3 = *reinterpret_cast<const float4*>(&g_scores[(size_t)(bbase + j0 + 3) * 4]);

    #pragma unroll
    for (int r = 0; r < 8; r++) {
        const int row = r0 + r;
        const float4 s = *reinterpret_cast<const float4*>(&g_scores[(size_t)row * 4]);
        const float d0 = s.x + bc0;
        const float d1 = s.y + bc1;
        float4 o0, o1;
        o0.x = d0 + h0.z; o0.y = d1 + h0.w;
        o0.z = d0 + h1.z; o0.w = d1 + h1.w;
        o1.x = d0 + h2.z; o1.y = d1 + h2.w;
        o1.z = d0 + h3.z; o1.w = d1 + h3.w;
        float* orow = out + (size_t)row * 2048;
        *reinterpret_cast<float4*>(orow + (size_t)j0 * 2)     = o0;
        *reinterpret_cast<float4*>(orow + (size_t)j0 * 2 + 4) = o1;
    }
}

// ---------------- launch ----------------
extern "C" void kernel_launch(void* const* d_in, const int* in_sizes, int n_in,
                              void* d_out, int out_size) {
    const float* hidden = (const float*)d_in[0];
    const float* Wd     = (const float*)d_in[1];
    const float* bd     = (const float*)d_in[2];
    const float* Wh     = (const float*)d_in[3];
    const float* bh     = (const float*)d_in[4];
    const float* Wc     = (const float*)d_in[5];
    const float* bc     = (const float*)d_in[6];
    float* out = (float*)d_out;

    cudaFuncSetAttribute(gemm_mma, cudaFuncAttributeMaxDynamicSharedMemorySize, SMEM_TOTAL);

    convert_A<<<(R_TOTAL * KDIM) / (256 * 4), 256>>>(hidden);
    convert_W<<<NPAD, 256>>>(Wd, Wh);
    zero_scores<<<R_TOTAL * 4 / 1024, 256>>>();
    gemm_mma<<<dim3(NPAD / 128, R_TOTAL / 128), 512, SMEM_TOTAL>>>(bd, bh, Wc);
    broadcast_kernel<<<R_TOTAL / 8, 256>>>(bc, out);
}